// round 16
// baseline (speedup 1.0000x reference)
#include <cuda_runtime.h>
#include <cuda_fp16.h>
#include <cuda_bf16.h>

// Inputs (metadata order):
// 0: nbr_ids   [N]  int32
// 1: seg_ids   [N]  int32   (unused; degree = N/G)
// 2: batch_idx [G]  int32
// 3: pos_idx   [G]  int32
// 4: s_tem     [B]  int32
// 5: r_tem     [B]  int32
// 6: dt_flat   [G]  float32
// 7: ent_embeds [NUM_ENTS*D] float32
// 8: rel_embeds [NUM_RELS*D] float32
// Output: [ s_embed_seq (G*3D floats) | s_hist_dt_seq (G floats) ]

#define F16_CAP  (16 * 1024 * 1024)       // halves  (32 MB)
#define I8_CAPU  (4 * 1024 * 1024)        // uints   (16 MB) -> 65536 rows of 256 B
#define MAX_ROWS 65536

__device__ __align__(256) __half  g_ent_f16[F16_CAP];
__device__ __align__(256) unsigned g_ent_i8u[I8_CAPU];   // biased int8 (u = q+128)
__device__ __align__(256) unsigned short g_scale_h[MAX_ROWS]; // fp16 absmax/127

// ---------------- convert: fp32 row -> fp16 row + biased int8 row + scale ----
// One warp per 256-dim row: lane covers 8 dims (2 float4). absmax via shfl.
__global__ void __launch_bounds__(256)
quantize_kernel(const float4* __restrict__ src, int nrows)
{
    const int row  = blockIdx.x * 8 + (threadIdx.x >> 5);
    const int lane = threadIdx.x & 31;
    if (row >= nrows) return;

    const float4* p = src + (size_t)row * 64 + lane * 2;
    float4 a = p[0], b = p[1];

    float m = fabsf(a.x);
    m = fmaxf(m, fabsf(a.y)); m = fmaxf(m, fabsf(a.z)); m = fmaxf(m, fabsf(a.w));
    m = fmaxf(m, fabsf(b.x)); m = fmaxf(m, fabsf(b.y));
    m = fmaxf(m, fabsf(b.z)); m = fmaxf(m, fabsf(b.w));
#pragma unroll
    for (int o = 16; o; o >>= 1) m = fmaxf(m, __shfl_xor_sync(0xffffffffu, m, o));

    const float scale = m * (1.0f / 127.0f);
    const float inv   = (m > 0.f) ? (127.0f / m) : 0.f;

    // fp16 row (linear layout, row = 32 uint4)
    {
        __half2 h0 = __floats2half2_rn(a.x, a.y);
        __half2 h1 = __floats2half2_rn(a.z, a.w);
        __half2 h2 = __floats2half2_rn(b.x, b.y);
        __half2 h3 = __floats2half2_rn(b.z, b.w);
        uint4 o;
        o.x = *reinterpret_cast<unsigned*>(&h0);
        o.y = *reinterpret_cast<unsigned*>(&h1);
        o.z = *reinterpret_cast<unsigned*>(&h2);
        o.w = *reinterpret_cast<unsigned*>(&h3);
        reinterpret_cast<uint4*>(g_ent_f16)[(size_t)row * 32 + lane] = o;
    }
    // biased int8 row (row = 32 uint2 = 256 B); u = round(x*inv)+128 in [1,255]
    {
        int q0 = __float2int_rn(a.x * inv) + 128, q1 = __float2int_rn(a.y * inv) + 128;
        int q2 = __float2int_rn(a.z * inv) + 128, q3 = __float2int_rn(a.w * inv) + 128;
        int q4 = __float2int_rn(b.x * inv) + 128, q5 = __float2int_rn(b.y * inv) + 128;
        int q6 = __float2int_rn(b.z * inv) + 128, q7 = __float2int_rn(b.w * inv) + 128;
        unsigned u0 = (unsigned)(q0 & 255) | ((unsigned)(q1 & 255) << 8) |
                      ((unsigned)(q2 & 255) << 16) | ((unsigned)(q3 & 255) << 24);
        unsigned u1 = (unsigned)(q4 & 255) | ((unsigned)(q5 & 255) << 8) |
                      ((unsigned)(q6 & 255) << 16) | ((unsigned)(q7 & 255) << 24);
        reinterpret_cast<uint2*>(g_ent_i8u)[(size_t)row * 32 + lane] = make_uint2(u0, u1);
    }
    if (lane == 0) {
        __half hs = __float2half_rn(scale);
        g_scale_h[row] = *reinterpret_cast<unsigned short*>(&hs);
    }
}

// ---------------- Fast path: hybrid int8/fp16 gather (R7/R13 geometry) -------
// 4 groups x 64 lanes per 256-thread CTA, grid G/4. Lane t owns dims 4t..4t+3.
// Neighbors 0..15: int8 rows (uint/lane) decoded via magic-fp16 (PRMT 0x64 ->
// 1024+u; HSUB2 1152 -> exact int q; HFMA2 by row scale).
// Neighbors 16..31: fp16 rows (uint2/lane), HADD2 as before.
// Dual banks per half; final combine + /32 in fp32. subj/rel/dt fused.
__global__ void __launch_bounds__(256)
agg_hybrid_kernel(const int* __restrict__ nbr_ids,
                  const int* __restrict__ batch_idx,
                  const int* __restrict__ pos_idx,
                  const int* __restrict__ s_tem,
                  const int* __restrict__ r_tem,
                  const float* __restrict__ dt_flat,
                  const float4* __restrict__ ent,    // fp32, stride 64 f4
                  const float4* __restrict__ rel,
                  float4* __restrict__ out_embed,    // stride 192 f4
                  float* __restrict__ out_dt,
                  int S)
{
    const int tid  = threadIdx.x;
    const int grp  = tid >> 6;
    const int lane = tid & 31;
    const int t    = tid & 63;
    const int g    = (blockIdx.x << 2) + grp;

    const int my_id = __ldg(&nbr_ids[(g << 5) + lane]);
    unsigned my_s2;
    {
        unsigned sh = (unsigned)g_scale_h[my_id];
        my_s2 = sh | (sh << 16);               // half2{s, s}
    }

    const uint2* tabh = reinterpret_cast<const uint2*>(g_ent_f16);  // row = 64 uint2
    const unsigned* tab8 = g_ent_i8u;                                // row = 64 uint

    const __half2 hz = __half2half2(__ushort_as_half(0));
    const __half2 c1152 = __floats2half2_rn(1152.f, 1152.f);

    // int8 banks (I even, J odd) and fp16 banks (F even, E odd); x=dims 0,1 y=2,3
    __half2 I0 = hz, I1 = hz, J0 = hz, J1 = hz;
    __half2 F0 = hz, F1 = hz, E0 = hz, E1 = hz;

#pragma unroll
    for (int j = 0; j < 16; j += 2) {
        int idA = __shfl_sync(0xffffffffu, my_id, j);
        unsigned sA = __shfl_sync(0xffffffffu, my_s2, j);
        int idB = __shfl_sync(0xffffffffu, my_id, j + 1);
        unsigned sB = __shfl_sync(0xffffffffu, my_s2, j + 1);
        unsigned vA = __ldg(&tab8[(idA << 6) + t]);    // 4 biased bytes
        unsigned vB = __ldg(&tab8[(idB << 6) + t]);

        unsigned la = __byte_perm(vA, 0x64646464u, 0x4140);
        unsigned ha = __byte_perm(vA, 0x64646464u, 0x4342);
        unsigned lb = __byte_perm(vB, 0x64646464u, 0x4140);
        unsigned hb = __byte_perm(vB, 0x64646464u, 0x4342);

        __half2 qa0 = __hsub2(*reinterpret_cast<__half2*>(&la), c1152);
        __half2 qa1 = __hsub2(*reinterpret_cast<__half2*>(&ha), c1152);
        __half2 qb0 = __hsub2(*reinterpret_cast<__half2*>(&lb), c1152);
        __half2 qb1 = __hsub2(*reinterpret_cast<__half2*>(&hb), c1152);

        I0 = __hfma2(qa0, *reinterpret_cast<__half2*>(&sA), I0);
        I1 = __hfma2(qa1, *reinterpret_cast<__half2*>(&sA), I1);
        J0 = __hfma2(qb0, *reinterpret_cast<__half2*>(&sB), J0);
        J1 = __hfma2(qb1, *reinterpret_cast<__half2*>(&sB), J1);
    }

#pragma unroll
    for (int j = 16; j < 32; j += 2) {
        int idA = __shfl_sync(0xffffffffu, my_id, j);
        int idB = __shfl_sync(0xffffffffu, my_id, j + 1);
        uint2 va = __ldg(&tabh[(idA << 6) + t]);       // 4 halves
        uint2 vb = __ldg(&tabh[(idB << 6) + t]);
        F0 = __hadd2(F0, *reinterpret_cast<const __half2*>(&va.x));
        F1 = __hadd2(F1, *reinterpret_cast<const __half2*>(&va.y));
        E0 = __hadd2(E0, *reinterpret_cast<const __half2*>(&vb.x));
        E1 = __hadd2(E1, *reinterpret_cast<const __half2*>(&vb.y));
    }

    const float inv = 1.0f / 32.0f;
    float2 i0 = __half22float2(I0), j0 = __half22float2(J0);
    float2 i1 = __half22float2(I1), j1 = __half22float2(J1);
    float2 f0 = __half22float2(F0), e0 = __half22float2(E0);
    float2 f1 = __half22float2(F1), e1 = __half22float2(E1);
    float4 m = make_float4((i0.x + j0.x + f0.x + e0.x) * inv,
                           (i0.y + j0.y + f0.y + e0.y) * inv,
                           (i1.x + j1.x + f1.x + e1.x) * inv,
                           (i1.y + j1.y + f1.y + e1.y) * inv);

    const int b = batch_idx[g];
    const int p = pos_idx[g];
    const int obase = (b * S + p) * 192;

    float4 sv = __ldg(&ent[(s_tem[b] << 6) + t]);
    float4 rv = __ldg(&rel[(r_tem[b] << 6) + t]);

    __stcs(&out_embed[obase + t],       m);
    __stcs(&out_embed[obase + 64 + t],  sv);
    __stcs(&out_embed[obase + 128 + t], rv);

    if (t == 0) out_dt[b * S + p] = dt_flat[g];
}

// ---------------- Generic fallback: any DEG / D, fp32 ----------------
__global__ void agg_generic_kernel(const int* __restrict__ nbr_ids,
                                   const int* __restrict__ batch_idx,
                                   const int* __restrict__ pos_idx,
                                   const int* __restrict__ s_tem,
                                   const int* __restrict__ r_tem,
                                   const float* __restrict__ dt_flat,
                                   const float* __restrict__ ent,
                                   const float* __restrict__ rel,
                                   float* __restrict__ out_embed,
                                   float* __restrict__ out_dt,
                                   int S, int D, int DEG)
{
    const int g = blockIdx.x;
    const int b = batch_idx[g];
    const int p = pos_idx[g];
    const long obase = (long)(b * S + p) * (3L * D);
    const float inv = 1.0f / (float)DEG;

    for (int d = threadIdx.x; d < D; d += blockDim.x) {
        float sum = 0.f;
        for (int j = 0; j < DEG; ++j) {
            int id = nbr_ids[(long)g * DEG + j];
            sum += ent[(long)id * D + d];
        }
        out_embed[obase + d]         = sum * inv;
        out_embed[obase + D + d]     = ent[(long)s_tem[b] * D + d];
        out_embed[obase + 2 * D + d] = rel[(long)r_tem[b] * D + d];
    }
    if (threadIdx.x == 0) out_dt[b * S + p] = dt_flat[g];
}

extern "C" void kernel_launch(void* const* d_in, const int* in_sizes, int n_in,
                              void* d_out, int out_size)
{
    const int*   nbr_ids   = (const int*)  d_in[0];
    const int*   batch_idx = (const int*)  d_in[2];
    const int*   pos_idx   = (const int*)  d_in[3];
    const int*   s_tem     = (const int*)  d_in[4];
    const int*   r_tem     = (const int*)  d_in[5];
    const float* dt_flat   = (const float*)d_in[6];
    const float* ent       = (const float*)d_in[7];
    const float* rel       = (const float*)d_in[8];

    const int N    = in_sizes[0];
    const int G    = in_sizes[2];
    const int B    = in_sizes[4];
    const int ENTD = in_sizes[7];          // NUM_ENTS * D
    const int DEG  = N / G;
    const int S    = G / B;
    const int D    = ((out_size / G) - 1) / 3;
    const int nrows = (D > 0) ? ENTD / D : 0;

    float* out_embed = (float*)d_out;
    float* out_dt    = (float*)d_out + (long)G * 3L * D;

    if (DEG == 32 && D == 256 && (G & 3) == 0 && (ENTD % 256) == 0 &&
        ENTD <= F16_CAP && nrows <= MAX_ROWS) {
        quantize_kernel<<<(nrows + 7) / 8, 256>>>((const float4*)ent, nrows);
        agg_hybrid_kernel<<<G / 4, 256>>>(nbr_ids, batch_idx, pos_idx, s_tem, r_tem,
                                          dt_flat, (const float4*)ent, (const float4*)rel,
                                          (float4*)out_embed, out_dt, S);
    } else {
        agg_generic_kernel<<<G, 256>>>(nbr_ids, batch_idx, pos_idx, s_tem, r_tem,
                                       dt_flat, ent, rel, out_embed, out_dt,
                                       S, D, DEG);
    }
}

// round 17
// speedup vs baseline: 1.1233x; 1.1233x over previous
#include <cuda_runtime.h>
#include <cuda_fp16.h>
#include <cuda_bf16.h>

// Inputs (metadata order):
// 0: nbr_ids   [N]  int32
// 1: seg_ids   [N]  int32   (unused; degree = N/G)
// 2: batch_idx [G]  int32
// 3: pos_idx   [G]  int32
// 4: s_tem     [B]  int32
// 5: r_tem     [B]  int32
// 6: dt_flat   [G]  float32
// 7: ent_embeds [NUM_ENTS*D] float32
// 8: rel_embeds [NUM_RELS*D] float32
// Output: [ s_embed_seq (G*3D floats) | s_hist_dt_seq (G floats) ]

#define F16_CAP (16 * 1024 * 1024)
__device__ __align__(256) __half g_ent_f16[F16_CAP];

// 256-bit evict-last load (the only legal .L2::evict_last shape on sm_100a).
static __device__ __forceinline__ void ldg_el_v8(const unsigned* p,
                                                 unsigned* v /* [8] */)
{
    asm volatile("ld.global.nc.L2::evict_last.v8.b32 "
                 "{%0,%1,%2,%3,%4,%5,%6,%7}, [%8];"
                 : "=r"(v[0]), "=r"(v[1]), "=r"(v[2]), "=r"(v[3]),
                   "=r"(v[4]), "=r"(v[5]), "=r"(v[6]), "=r"(v[7])
                 : "l"(p));
}

// ---------------- fp32 -> fp16 table conversion ----------------
// One 32 B (v8.b32) evict-last load per thread -> one uint4 fp16 store.
__global__ void __launch_bounds__(256)
convert_f16_kernel(const unsigned* __restrict__ src, int n8)
{
    int i = blockIdx.x * 256 + threadIdx.x;
    if (i >= n8) return;
    unsigned v[8];
    ldg_el_v8(src + 8 * (size_t)i, v);
    __half2 h0 = __floats2half2_rn(__uint_as_float(v[0]), __uint_as_float(v[1]));
    __half2 h1 = __floats2half2_rn(__uint_as_float(v[2]), __uint_as_float(v[3]));
    __half2 h2 = __floats2half2_rn(__uint_as_float(v[4]), __uint_as_float(v[5]));
    __half2 h3 = __floats2half2_rn(__uint_as_float(v[6]), __uint_as_float(v[7]));
    uint4 o;
    o.x = *reinterpret_cast<unsigned*>(&h0);
    o.y = *reinterpret_cast<unsigned*>(&h1);
    o.z = *reinterpret_cast<unsigned*>(&h2);
    o.w = *reinterpret_cast<unsigned*>(&h3);
    reinterpret_cast<uint4*>(g_ent_f16)[i] = o;
}

// ---------------- Fast path (locked optimum): DEG==32, D==256 ----------------
// 4 groups x 64 lanes per 256-thread CTA, grid G/4, uint2 (8 B) gathers,
// ids via intra-warp shfl, HADD2 dual-bank accumulation merged in fp32.
// subj/rel/dt fused (priced at the L2-cap path). 32 regs = full occupancy.
// Measured: 24.0 us kernel, 32.77 us total (best of 16 rounds).
__global__ void __launch_bounds__(256)
agg_f16_kernel(const int* __restrict__ nbr_ids,
               const int* __restrict__ batch_idx,
               const int* __restrict__ pos_idx,
               const int* __restrict__ s_tem,
               const int* __restrict__ r_tem,
               const float* __restrict__ dt_flat,
               const float4* __restrict__ ent,    // fp32, row stride 64 float4
               const float4* __restrict__ rel,    // fp32, row stride 64 float4
               float4* __restrict__ out_embed,    // row stride 192 float4
               float* __restrict__ out_dt,
               int S)
{
    const int tid  = threadIdx.x;
    const int grp  = tid >> 6;          // 0..3 group within block
    const int lane = tid & 31;          // lane within warp
    const int t    = tid & 63;          // dim-lane within group (owns 4 dims)
    const int g    = (blockIdx.x << 2) + grp;

    // both warps of the group load the same ids (same addresses -> L1 broadcast)
    const int my_id = __ldg(&nbr_ids[(g << 5) + lane]);

    const uint2* tab = reinterpret_cast<const uint2*>(g_ent_f16); // row = 64 uint2

    const __half2 hz = __half2half2(__ushort_as_half(0));
    __half2 a0 = hz, a1 = hz, b0 = hz, b1 = hz;   // even bank (a), odd bank (b)

#pragma unroll
    for (int j = 0; j < 32; j += 2) {
        int idA = __shfl_sync(0xffffffffu, my_id, j);
        int idB = __shfl_sync(0xffffffffu, my_id, j + 1);
        uint2 va = __ldg(&tab[(idA << 6) + t]);   // 8 B = 4 halves
        uint2 vb = __ldg(&tab[(idB << 6) + t]);
        a0 = __hadd2(a0, *reinterpret_cast<const __half2*>(&va.x));
        a1 = __hadd2(a1, *reinterpret_cast<const __half2*>(&va.y));
        b0 = __hadd2(b0, *reinterpret_cast<const __half2*>(&vb.x));
        b1 = __hadd2(b1, *reinterpret_cast<const __half2*>(&vb.y));
    }

    const float inv = 1.0f / 32.0f;
    float2 fa0 = __half22float2(a0), fb0 = __half22float2(b0);
    float2 fa1 = __half22float2(a1), fb1 = __half22float2(b1);
    float4 m = make_float4((fa0.x + fb0.x) * inv, (fa0.y + fb0.y) * inv,
                           (fa1.x + fb1.x) * inv, (fa1.y + fb1.y) * inv);

    const int b = batch_idx[g];
    const int p = pos_idx[g];
    const int obase = (b * S + p) * 192;   // 3*256/4 float4 per output row

    float4 sv = __ldg(&ent[(s_tem[b] << 6) + t]);
    float4 rv = __ldg(&rel[(r_tem[b] << 6) + t]);

    // streaming stores: write-once output; evict-first so tables stay resident
    __stcs(&out_embed[obase + t],       m);
    __stcs(&out_embed[obase + 64 + t],  sv);
    __stcs(&out_embed[obase + 128 + t], rv);

    if (t == 0) out_dt[b * S + p] = dt_flat[g];
}

// ---------------- Generic fallback: any DEG / D, fp32 ----------------
__global__ void agg_generic_kernel(const int* __restrict__ nbr_ids,
                                   const int* __restrict__ batch_idx,
                                   const int* __restrict__ pos_idx,
                                   const int* __restrict__ s_tem,
                                   const int* __restrict__ r_tem,
                                   const float* __restrict__ dt_flat,
                                   const float* __restrict__ ent,
                                   const float* __restrict__ rel,
                                   float* __restrict__ out_embed,
                                   float* __restrict__ out_dt,
                                   int S, int D, int DEG)
{
    const int g = blockIdx.x;
    const int b = batch_idx[g];
    const int p = pos_idx[g];
    const long obase = (long)(b * S + p) * (3L * D);
    const float inv = 1.0f / (float)DEG;

    for (int d = threadIdx.x; d < D; d += blockDim.x) {
        float sum = 0.f;
        for (int j = 0; j < DEG; ++j) {
            int id = nbr_ids[(long)g * DEG + j];
            sum += ent[(long)id * D + d];
        }
        out_embed[obase + d]         = sum * inv;
        out_embed[obase + D + d]     = ent[(long)s_tem[b] * D + d];
        out_embed[obase + 2 * D + d] = rel[(long)r_tem[b] * D + d];
    }
    if (threadIdx.x == 0) out_dt[b * S + p] = dt_flat[g];
}

extern "C" void kernel_launch(void* const* d_in, const int* in_sizes, int n_in,
                              void* d_out, int out_size)
{
    const int*   nbr_ids   = (const int*)  d_in[0];
    const int*   batch_idx = (const int*)  d_in[2];
    const int*   pos_idx   = (const int*)  d_in[3];
    const int*   s_tem     = (const int*)  d_in[4];
    const int*   r_tem     = (const int*)  d_in[5];
    const float* dt_flat   = (const float*)d_in[6];
    const float* ent       = (const float*)d_in[7];
    const float* rel       = (const float*)d_in[8];

    const int N    = in_sizes[0];
    const int G    = in_sizes[2];
    const int B    = in_sizes[4];
    const int ENTD = in_sizes[7];          // NUM_ENTS * D
    const int DEG  = N / G;
    const int S    = G / B;
    const int D    = ((out_size / G) - 1) / 3;

    float* out_embed = (float*)d_out;
    float* out_dt    = (float*)d_out + (long)G * 3L * D;

    if (DEG == 32 && D == 256 && (G & 3) == 0 && ENTD <= F16_CAP && (ENTD & 7) == 0) {
        const int n8 = ENTD >> 3;
        convert_f16_kernel<<<(n8 + 255) / 256, 256>>>((const unsigned*)ent, n8);
        agg_f16_kernel<<<G / 4, 256>>>(nbr_ids, batch_idx, pos_idx, s_tem, r_tem,
                                       dt_flat, (const float4*)ent, (const float4*)rel,
                                       (float4*)out_embed, out_dt, S);
    } else {
        agg_generic_kernel<<<G, 256>>>(nbr_ids, batch_idx, pos_idx, s_tem, r_tem,
                                       dt_flat, ent, rel, out_embed, out_dt,
                                       S, D, DEG);
    }
}